// round 17
// baseline (speedup 1.0000x reference)
#include <cuda_runtime.h>
#include <math.h>
#include <stdint.h>

// ChordalPCWeightTransform — R16: eager cp.async loads + TMA bulk store, 512-row tile.
// Math identity (R4): the two per-label rolls cancel on the data and rotate
// only the weight vector:
//   out[b,l,p] = softmax_p( x[b,l,p] * w[(p - root) mod 12] ), p<12; w[12] at p=12
//   root = (row / 12) % 12
//
// Winning pair from the R5..R15 2x2: eager per-thread cp.async.cg loads
// (intra-CTA staggering, full MLP) + single cp.async.bulk burst store.
// R16 doubles the tile to 512 rows: 2x store burst length, half the
// barriers/TMA-issues/drains per byte, occupancy preserved (26.75 KB x 8
// CTAs = 214 KB <= 228 KB).

#define P 13
#define RPB 256
#define ROWS_PER_TILE 512
#define TILE_FLOATS (ROWS_PER_TILE * P)     // 6656 floats = 26624 B
#define TILE_BYTES (TILE_FLOATS * 4)
#define VEC4_PER_TILE (TILE_FLOATS / 4)     // 1664 = 6*256 + 128

__device__ __forceinline__ void cp_async16(uint32_t saddr, const void* gptr) {
    asm volatile("cp.async.cg.shared.global [%0], [%1], 16;"
                 :: "r"(saddr), "l"(gptr));
}

__global__ __launch_bounds__(RPB)
void chordal_softmax_kernel(const float* __restrict__ x,
                            const float* __restrict__ w,
                            float* __restrict__ out)
{
    __shared__ alignas(128) float tile[TILE_FLOATS];
    __shared__ float ws[P];

    const int tid = threadIdx.x;
    if (tid < P) ws[tid] = __ldg(&w[tid]);

    const long long base = (long long)blockIdx.x * TILE_FLOATS;
    const uint32_t tile_a = (uint32_t)__cvta_generic_to_shared(tile);

    // ---- eager async staging: global -> smem (6-7 vec4/thread, full MLP) ----
    {
        const float4* g = (const float4*)(x + base);
#pragma unroll
        for (int i = 0; i < 6; i++) {
            const int idx = tid + i * RPB;
            cp_async16(tile_a + (uint32_t)idx * 16, g + idx);
        }
        if (tid < (VEC4_PER_TILE - 6 * RPB)) {          // 128 remainder
            const int idx = tid + 6 * RPB;
            cp_async16(tile_a + (uint32_t)idx * 16, g + idx);
        }
        asm volatile("cp.async.commit_group;");
        asm volatile("cp.async.wait_group 0;");
    }
    __syncthreads();

    // ---- per-thread weighted softmax, 2 rows per thread, in place ----
#pragma unroll
    for (int rr = 0; rr < 2; rr++) {
        const int lr   = tid + rr * RPB;                // local row 0..511
        const int row  = blockIdx.x * ROWS_PER_TILE + lr;
        const int root = (row / 12) % 12;

        float v[P];
        float m = -INFINITY;
#pragma unroll
        for (int p = 0; p < P; p++) {
            int wi;
            if (p == 12) {
                wi = 12;
            } else {
                wi = p - root;
                if (wi < 0) wi += 12;
            }
            v[p] = tile[lr * P + p] * ws[wi];
            m = fmaxf(m, v[p]);
        }
        float s = 0.0f;
#pragma unroll
        for (int p = 0; p < P; p++) { v[p] = __expf(v[p] - m); s += v[p]; }
        const float r = __frcp_rn(s);
#pragma unroll
        for (int p = 0; p < P; p++) tile[lr * P + p] = v[p] * r;
    }
    __syncthreads();   // all rows in smem before the bulk store reads them

    // ---- single bulk burst store: smem -> global (26624 B, one TMA op) ----
    if (tid == 0) {
        asm volatile("fence.proxy.async.shared::cta;" ::: "memory");
        asm volatile("cp.async.bulk.global.shared::cta.bulk_group [%0], [%1], %2;"
                     :: "l"(out + base), "r"(tile_a), "r"((uint32_t)TILE_BYTES)
                     : "memory");
        asm volatile("cp.async.bulk.commit_group;");
        // smem must stay live until the TMA engine has read it out.
        asm volatile("cp.async.bulk.wait_group.read 0;" ::: "memory");
    }
}

extern "C" void kernel_launch(void* const* d_in, const int* in_sizes, int n_in,
                              void* d_out, int out_size)
{
    const float* x = (const float*)d_in[0];   // chordal_pc_vector [65536,144,13]
    const float* w = (const float*)d_in[1];   // scale_degree_weight [13]
    float* out = (float*)d_out;

    const long long total = (long long)in_sizes[0];   // 122,683,392
    const int nblocks = (int)(total / TILE_FLOATS);   // 18432

    // Full smem carveout so 8 CTAs/SM fit (8 * ~26.8 KB).
    cudaFuncSetAttribute(chordal_softmax_kernel,
                         cudaFuncAttributePreferredSharedMemoryCarveout, 100);

    chordal_softmax_kernel<<<nblocks, RPB>>>(x, w, out);
}